// round 2
// baseline (speedup 1.0000x reference)
#include <cuda_runtime.h>
#include <math.h>

#define NB   256
#define LCC  400
#define LQQ  50
#define DD   128
#define SROW 51      // padded S row stride (floats)
#define XPAD 132     // padded row stride for D-vectors
#define QP   52      // padded q stride for transposed Yq
#define CCHUNK 128
#define NT   1024

// smem offsets (floats)
#define OFF_S    0                    // 400*51   = 20400
#define OFF_XQ   20400                // 52*132   = 6864
#define OFF_YQT  27264                // 128*52   = 6656
#define OFF_XC   33920                // 128*132  = 16896
#define OFF_TMP  (OFF_XC + 4096)      // 50*132 = 6600, aliased inside sXc (rows >= 31)
#define OFF_SB   OFF_XC               // 64*50 = 3200, aliased at sXc start
#define OFF_RMAX 50816                // 400
#define OFF_RINV 51216                // 400
#define OFF_CMAX 51616                // 52
#define OFF_CINV 51668                // 52
#define OFF_QW1  51720                // 52
#define SMEM_FLOATS 51772             // 207088 bytes

#define RES_ELEMS ((size_t)NB * LCC * 4 * DD)      // 52,428,800

typedef unsigned long long u64;

__device__ __forceinline__ u64 pack2b(float v) {
    u64 r; asm("mov.b64 %0, {%1, %1};" : "=l"(r) : "f"(v)); return r;
}
__device__ __forceinline__ u64 pack2f(float a, float b) {
    u64 r; asm("mov.b64 %0, {%1, %2};" : "=l"(r) : "f"(a), "f"(b)); return r;
}
__device__ __forceinline__ void fma2(u64 &d, u64 a, u64 b) {
    asm("fma.rn.f32x2 %0, %1, %2, %3;" : "=l"(d) : "l"(a), "l"(b), "l"(d));
}
__device__ __forceinline__ float2 unpk(u64 v) {
    float2 r; asm("mov.b64 {%0, %1}, %2;" : "=f"(r.x), "=f"(r.y) : "l"(v)); return r;
}

__global__ __launch_bounds__(NT, 1)
void cqa_kernel(const float* __restrict__ xc_g, const float* __restrict__ xq_g,
                const float* __restrict__ W0, const float* __restrict__ W1,
                const float* __restrict__ W2, const int* __restrict__ clen_g,
                const int* __restrict__ qlen_g, float* __restrict__ out)
{
    extern __shared__ float sm[];
    const int b   = blockIdx.x;
    const int tid = threadIdx.x;
    const float* xcB = xc_g + (size_t)b * LCC * DD;
    const float* xqB = xq_g + (size_t)b * LQQ * DD;
    const int clen = clen_g[b];
    const int qlen = qlen_g[b];

    float* sS    = sm + OFF_S;
    float* sXq   = sm + OFF_XQ;
    float* sYqT  = sm + OFF_YQT;
    float* sXc   = sm + OFF_XC;
    float* sTmp  = sm + OFF_TMP;
    float* sSb   = sm + OFF_SB;
    float* sRMax = sm + OFF_RMAX;
    float* sRInv = sm + OFF_RINV;
    float* sCMax = sm + OFF_CMAX;
    float* sCInv = sm + OFF_CINV;
    float* sQW1  = sm + OFF_QW1;

    // ---------------- Phase 0: stage xq + build YqT = (xq*W2 + W0)^T ----------------
    for (int idx = tid; idx < LQQ * 32; idx += NT) {
        int q  = idx >> 5;
        int c4 = (idx & 31) * 4;
        float4 v  = *(const float4*)&xqB[q * DD + c4];
        *(float4*)&sXq[q * XPAD + c4] = v;
        float4 w2 = *(const float4*)&W2[c4];
        float4 w0 = *(const float4*)&W0[c4];
        sYqT[(c4 + 0) * QP + q] = fmaf(v.x, w2.x, w0.x);
        sYqT[(c4 + 1) * QP + q] = fmaf(v.y, w2.y, w0.y);
        sYqT[(c4 + 2) * QP + q] = fmaf(v.z, w2.z, w0.z);
        sYqT[(c4 + 3) * QP + q] = fmaf(v.w, w2.w, w0.w);
    }
    __syncthreads();
    // qW1[q] = xq[q] . W1
    if (tid < LQQ) {
        float s = 0.f;
        #pragma unroll 8
        for (int d = 0; d < DD; d += 4) {
            float4 xv = *(const float4*)&sXq[tid * XPAD + d];
            float4 wv = *(const float4*)&W1[d];
            s = fmaf(xv.x, wv.x, s); s = fmaf(xv.y, wv.y, s);
            s = fmaf(xv.z, wv.z, s); s = fmaf(xv.w, wv.w, s);
        }
        sQW1[tid] = s;
    }
    if (tid >= LQQ && tid < QP) sQW1[tid] = 0.f;

    // ---------------- Phase 1: S[c,q] = qW1[q] + xc[c,:] . YqT[:,q] ----------------
    // tiles: 2 c x 4 q per thread; 13 q-groups x 64 c-groups = 832 active threads
    for (int cb = 0; cb < LCC; cb += CCHUNK) {
        const int cn = min(CCHUNK, LCC - cb);
        __syncthreads();
        for (int idx = tid; idx < cn * 32; idx += NT) {
            int r  = idx >> 5;
            int c4 = (idx & 31) * 4;
            *(float4*)&sXc[r * XPAD + c4] = *(const float4*)&xcB[(size_t)(cb + r) * DD + c4];
        }
        __syncthreads();
        const int qg = tid % 13, cg = tid / 13;
        if (cg < 64) {
            const int q0 = qg * 4, c0 = cg * 2;
            if (c0 < cn) {
                const int ci1 = min(c0 + 1, cn - 1);
                u64 a0lo = pack2f(sQW1[q0], sQW1[q0 + 1]);
                u64 a0hi = pack2f(sQW1[q0 + 2], sQW1[q0 + 3]);
                u64 a1lo = a0lo, a1hi = a0hi;
                #pragma unroll 4
                for (int d4 = 0; d4 < DD; d4 += 4) {
                    float4 x0 = *(const float4*)&sXc[c0  * XPAD + d4];
                    float4 x1 = *(const float4*)&sXc[ci1 * XPAD + d4];
                    const float* xa0 = (const float*)&x0;
                    const float* xa1 = (const float*)&x1;
                    #pragma unroll
                    for (int dd = 0; dd < 4; ++dd) {
                        longlong2 yv = *(const longlong2*)&sYqT[(d4 + dd) * QP + q0];
                        u64 v0 = pack2b(xa0[dd]);
                        u64 v1 = pack2b(xa1[dd]);
                        fma2(a0lo, v0, (u64)yv.x); fma2(a0hi, v0, (u64)yv.y);
                        fma2(a1lo, v1, (u64)yv.x); fma2(a1hi, v1, (u64)yv.y);
                    }
                }
                {
                    float* row = &sS[(cb + c0) * SROW + q0];
                    float2 p = unpk(a0lo);
                    row[0] = p.x; row[1] = p.y;
                    p = unpk(a0hi);
                    if (q0 + 2 < LQQ) row[2] = p.x;
                    if (q0 + 3 < LQQ) row[3] = p.y;
                }
                if (c0 + 1 < cn) {
                    float* row = &sS[(cb + c0 + 1) * SROW + q0];
                    float2 p = unpk(a1lo);
                    row[0] = p.x; row[1] = p.y;
                    p = unpk(a1hi);
                    if (q0 + 2 < LQQ) row[2] = p.x;
                    if (q0 + 3 < LQQ) row[3] = p.y;
                }
            }
        }
    }
    __syncthreads();

    // ---------------- Phase 2: row stats + S_bar -> gmem ----------------
    if (tid < LCC) {
        const float* row = &sS[tid * SROW];
        float m = -3.0e38f;
        for (int q = 0; q < LQQ; ++q) {
            float v = row[q] - (q < qlen ? 0.f : 1e12f);
            m = fmaxf(m, v);
        }
        float sum = 0.f;
        for (int q = 0; q < LQQ; ++q) {
            float v = row[q] - (q < qlen ? 0.f : 1e12f);
            sum += __expf(v - m);
        }
        sRMax[tid] = m;
        sRInv[tid] = 1.f / sum;
    }
    __syncthreads();
    float* sbar_g = out + RES_ELEMS + (size_t)b * LCC * LQQ;
    for (int idx = tid; idx < LCC * LQQ; idx += NT) {
        int c = idx / LQQ, q = idx - c * LQQ;
        float v = sS[c * SROW + q] - (q < qlen ? 0.f : 1e12f);
        sbar_g[idx] = __expf(v - sRMax[c]) * sRInv[c];
    }

    // ---------------- Phase 3: column stats, transform S->P in place, S_T -> gmem ----------------
    {
        const int g = tid >> 4, s16 = tid & 15;
        float m = -3.0e38f;
        if (g < LQQ) {
            for (int c = s16; c < LCC; c += 16) {
                float v = sS[c * SROW + g] - (c < clen ? 0.f : 1e12f);
                m = fmaxf(m, v);
            }
        }
        m = fmaxf(m, __shfl_xor_sync(0xffffffffu, m, 1));
        m = fmaxf(m, __shfl_xor_sync(0xffffffffu, m, 2));
        m = fmaxf(m, __shfl_xor_sync(0xffffffffu, m, 4));
        m = fmaxf(m, __shfl_xor_sync(0xffffffffu, m, 8));
        float sum = 0.f;
        if (g < LQQ) {
            for (int c = s16; c < LCC; c += 16) {
                float v = sS[c * SROW + g] - (c < clen ? 0.f : 1e12f);
                sum += __expf(v - m);
            }
        }
        sum += __shfl_xor_sync(0xffffffffu, sum, 1);
        sum += __shfl_xor_sync(0xffffffffu, sum, 2);
        sum += __shfl_xor_sync(0xffffffffu, sum, 4);
        sum += __shfl_xor_sync(0xffffffffu, sum, 8);
        if (g < LQQ && s16 == 0) { sCMax[g] = m; sCInv[g] = 1.f / sum; }
    }
    __syncthreads();
    for (int idx = tid; idx < LCC * LQQ; idx += NT) {
        int c = idx / LQQ, q = idx - c * LQQ;
        float v = sS[c * SROW + q] - (c < clen ? 0.f : 1e12f);
        sS[c * SROW + q] = __expf(v - sCMax[q]) * sCInv[q];
    }
    __syncthreads();
    float* st_g = out + RES_ELEMS + (size_t)NB * LCC * LQQ + (size_t)b * LQQ * LCC;
    for (int idx = tid; idx < LQQ * LCC; idx += NT) {
        int q = idx / LCC, c = idx - q * LCC;
        st_g[idx] = sS[c * SROW + q];
    }

    // ---------------- Phase 4: tmp[q,d] = sum_c P[c,q] * xc[c,d] ----------------
    // 2 q per group x 32 d-threads; 25 q-groups = 800 active threads
    const int dg = tid & 31;
    {
        const int qg = tid >> 5;
        const int q0 = qg * 2;
        u64 t0lo = 0, t0hi = 0, t1lo = 0, t1hi = 0;
        for (int cb = 0; cb < LCC; cb += CCHUNK) {
            const int cn = min(CCHUNK, LCC - cb);
            __syncthreads();
            for (int idx = tid; idx < cn * 32; idx += NT) {
                int r  = idx >> 5;
                int c4 = (idx & 31) * 4;
                *(float4*)&sXc[r * XPAD + c4] = *(const float4*)&xcB[(size_t)(cb + r) * DD + c4];
            }
            __syncthreads();
            if (qg < 25) {
                #pragma unroll 2
                for (int c = 0; c < cn; ++c) {
                    longlong2 xv = *(const longlong2*)&sXc[c * XPAD + dg * 4];
                    const float* prow = &sS[(cb + c) * SROW + q0];
                    u64 P0 = pack2b(prow[0]);
                    u64 P1 = pack2b(prow[1]);
                    fma2(t0lo, P0, (u64)xv.x); fma2(t0hi, P0, (u64)xv.y);
                    fma2(t1lo, P1, (u64)xv.x); fma2(t1hi, P1, (u64)xv.y);
                }
            }
        }
        __syncthreads();
        if (qg < 25) {
            float2 p;
            p = unpk(t0lo); sTmp[q0 * XPAD + dg * 4 + 0] = p.x; sTmp[q0 * XPAD + dg * 4 + 1] = p.y;
            p = unpk(t0hi); sTmp[q0 * XPAD + dg * 4 + 2] = p.x; sTmp[q0 * XPAD + dg * 4 + 3] = p.y;
            p = unpk(t1lo); sTmp[(q0 + 1) * XPAD + dg * 4 + 0] = p.x; sTmp[(q0 + 1) * XPAD + dg * 4 + 1] = p.y;
            p = unpk(t1hi); sTmp[(q0 + 1) * XPAD + dg * 4 + 2] = p.x; sTmp[(q0 + 1) * XPAD + dg * 4 + 3] = p.y;
        }
    }

    // ---------------- Phase 5: c2q = Sb@xq, q2c = Sb@tmp, fused epilogue ----------------
    // 2 c per group x 32 d-threads, cb step 64 -> all 1024 threads active
    {
        const int cg = tid >> 5;
        for (int cb = 0; cb < LCC; cb += 64) {
            const int cn = min(64, LCC - cb);
            __syncthreads();
            for (int idx = tid; idx < cn * LQQ; idx += NT)
                sSb[idx] = sbar_g[(size_t)cb * LQQ + idx];
            __syncthreads();
            const int c0 = cg * 2;
            if (c0 < cn) {
                const int li1 = min(c0 + 1, cn - 1);
                u64 a10lo = 0, a10hi = 0, a11lo = 0, a11hi = 0;   // c2q rows c0, c0+1
                u64 a20lo = 0, a20hi = 0, a21lo = 0, a21hi = 0;   // q2c rows c0, c0+1
                #pragma unroll 2
                for (int q = 0; q < LQQ; ++q) {
                    longlong2 xqv = *(const longlong2*)&sXq[q * XPAD + dg * 4];
                    longlong2 tv  = *(const longlong2*)&sTmp[q * XPAD + dg * 4];
                    u64 S0 = pack2b(sSb[c0  * LQQ + q]);
                    u64 S1 = pack2b(sSb[li1 * LQQ + q]);
                    fma2(a10lo, S0, (u64)xqv.x); fma2(a10hi, S0, (u64)xqv.y);
                    fma2(a11lo, S1, (u64)xqv.x); fma2(a11hi, S1, (u64)xqv.y);
                    fma2(a20lo, S0, (u64)tv.x);  fma2(a20hi, S0, (u64)tv.y);
                    fma2(a21lo, S1, (u64)tv.x);  fma2(a21hi, S1, (u64)tv.y);
                }
                #define EPI(i, L1, H1, L2, H2)                                             \
                    if (c0 + (i) < cn) {                                                   \
                        int c = cb + c0 + (i);                                             \
                        float4 xcv = *(const float4*)&xcB[(size_t)c * DD + dg * 4];        \
                        float* orow = out + ((size_t)(b * LCC + c)) * (4 * DD);            \
                        float2 plo = unpk(L1), phi = unpk(H1);                             \
                        float4 A1 = make_float4(plo.x, plo.y, phi.x, phi.y);               \
                        plo = unpk(L2); phi = unpk(H2);                                    \
                        float4 A2 = make_float4(plo.x, plo.y, phi.x, phi.y);               \
                        *(float4*)&orow[dg * 4] = xcv;                                     \
                        *(float4*)&orow[DD + dg * 4] = A1;                                 \
                        float4 m1 = make_float4(xcv.x * A1.x, xcv.y * A1.y,                \
                                                xcv.z * A1.z, xcv.w * A1.w);               \
                        *(float4*)&orow[2 * DD + dg * 4] = m1;                             \
                        float4 m2 = make_float4(xcv.x * A2.x, xcv.y * A2.y,                \
                                                xcv.z * A2.z, xcv.w * A2.w);               \
                        *(float4*)&orow[3 * DD + dg * 4] = m2;                             \
                    }
                EPI(0, a10lo, a10hi, a20lo, a20hi)
                EPI(1, a11lo, a11hi, a21lo, a21hi)
                #undef EPI
            }
        }
    }
}

extern "C" void kernel_launch(void* const* d_in, const int* in_sizes, int n_in,
                              void* d_out, int out_size)
{
    const float* xc  = (const float*)d_in[0];
    const float* xq  = (const float*)d_in[1];
    const float* W0  = (const float*)d_in[2];
    const float* W1  = (const float*)d_in[3];
    const float* W2  = (const float*)d_in[4];
    const int* clen  = (const int*)d_in[5];
    const int* qlen  = (const int*)d_in[6];
    float* out = (float*)d_out;

    const int smem_bytes = SMEM_FLOATS * (int)sizeof(float);
    cudaFuncSetAttribute(cqa_kernel, cudaFuncAttributeMaxDynamicSharedMemorySize, smem_bytes);
    cqa_kernel<<<NB, NT, smem_bytes>>>(xc, xq, W0, W1, W2, clen, qlen, out);
}

// round 3
// speedup vs baseline: 1.4393x; 1.4393x over previous
#include <cuda_runtime.h>
#include <math.h>

#define NB   256
#define LCC  400
#define LQQ  50
#define DD   128
#define SROW 51      // padded S row stride (floats)
#define XPAD 132     // padded row stride for D-vectors
#define QP   52      // padded q stride for transposed Yq
#define CCHUNK 128
#define NT   512

// smem offsets (floats)
#define OFF_S    0                    // 400*51   = 20400
#define OFF_XQ   20400                // 52*132   = 6864
#define OFF_YQT  27264                // 128*52   = 6656
#define OFF_XC   33920                // 128*132  = 16896
#define OFF_TMP  (OFF_XC + 4096)      // 50*132 = 6600, aliased inside sXc (rows >= 31)
#define OFF_RMAX 50816                // 400  (becomes f[c] after M-reduce)
#define OFF_RINV 51216                // 400
#define OFF_CMAX 51616                // 52   (unused now)
#define OFF_CINV 51668                // 52
#define OFF_QW1  51720                // 52   (slot 50 reused for scalar M)
#define SMEM_FLOATS 51772             // 207088 bytes

#define RES_ELEMS ((size_t)NB * LCC * 4 * DD)      // 52,428,800

typedef unsigned long long u64;

__device__ __forceinline__ u64 pack2b(float v) {
    u64 r; asm("mov.b64 %0, {%1, %1};" : "=l"(r) : "f"(v)); return r;
}
__device__ __forceinline__ u64 pack2f(float a, float b) {
    u64 r; asm("mov.b64 %0, {%1, %2};" : "=l"(r) : "f"(a), "f"(b)); return r;
}
__device__ __forceinline__ void fma2(u64 &d, u64 a, u64 b) {
    asm("fma.rn.f32x2 %0, %1, %2, %3;" : "=l"(d) : "l"(a), "l"(b), "l"(d));
}
__device__ __forceinline__ void mul2(u64 &d, u64 a, u64 b) {
    asm("mul.rn.f32x2 %0, %1, %2;" : "=l"(d) : "l"(a), "l"(b));
}
__device__ __forceinline__ float2 unpk(u64 v) {
    float2 r; asm("mov.b64 {%0, %1}, %2;" : "=f"(r.x), "=f"(r.y) : "l"(v)); return r;
}

__global__ __launch_bounds__(NT, 1)
void cqa_kernel(const float* __restrict__ xc_g, const float* __restrict__ xq_g,
                const float* __restrict__ W0, const float* __restrict__ W1,
                const float* __restrict__ W2, const int* __restrict__ clen_g,
                const int* __restrict__ qlen_g, float* __restrict__ out)
{
    extern __shared__ float sm[];
    const int b   = blockIdx.x;
    const int tid = threadIdx.x;
    const float* xcB = xc_g + (size_t)b * LCC * DD;
    const float* xqB = xq_g + (size_t)b * LQQ * DD;
    const int clen = clen_g[b];
    const int qlen = qlen_g[b];

    float* sS    = sm + OFF_S;
    float* sXq   = sm + OFF_XQ;
    float* sYqT  = sm + OFF_YQT;
    float* sXc   = sm + OFF_XC;
    float* sTmp  = sm + OFF_TMP;
    float* sF    = sm + OFF_RMAX;   // rmax, then f[c]
    float* sRInv = sm + OFF_RINV;
    float* sCInv = sm + OFF_CINV;
    float* sQW1  = sm + OFF_QW1;

    // ---------------- Phase 0: stage xq + build YqT = (xq*W2 + W0)^T ----------------
    for (int idx = tid; idx < LQQ * 32; idx += NT) {
        int q  = idx >> 5;
        int c4 = (idx & 31) * 4;
        float4 v  = *(const float4*)&xqB[q * DD + c4];
        *(float4*)&sXq[q * XPAD + c4] = v;
        float4 w2 = *(const float4*)&W2[c4];
        float4 w0 = *(const float4*)&W0[c4];
        sYqT[(c4 + 0) * QP + q] = fmaf(v.x, w2.x, w0.x);
        sYqT[(c4 + 1) * QP + q] = fmaf(v.y, w2.y, w0.y);
        sYqT[(c4 + 2) * QP + q] = fmaf(v.z, w2.z, w0.z);
        sYqT[(c4 + 3) * QP + q] = fmaf(v.w, w2.w, w0.w);
    }
    __syncthreads();
    // qW1[q] = xq[q] . W1
    if (tid < LQQ) {
        float s = 0.f;
        #pragma unroll 8
        for (int d = 0; d < DD; d += 4) {
            float4 xv = *(const float4*)&sXq[tid * XPAD + d];
            float4 wv = *(const float4*)&W1[d];
            s = fmaf(xv.x, wv.x, s); s = fmaf(xv.y, wv.y, s);
            s = fmaf(xv.z, wv.z, s); s = fmaf(xv.w, wv.w, s);
        }
        sQW1[tid] = s;
    }
    if (tid >= LQQ && tid < QP) sQW1[tid] = 0.f;

    // ---------------- Phase 1: S[c,q] = qW1[q] + xc[c,:] . YqT[:,q] ----------------
    // 4c x 4q tiles, f32x2 over q pairs; 13 qg x 32 cg = 416 active threads
    for (int cb = 0; cb < LCC; cb += CCHUNK) {
        const int cn = min(CCHUNK, LCC - cb);
        __syncthreads();
        for (int idx = tid; idx < cn * 32; idx += NT) {
            int r  = idx >> 5;
            int c4 = (idx & 31) * 4;
            *(float4*)&sXc[r * XPAD + c4] = *(const float4*)&xcB[(size_t)(cb + r) * DD + c4];
        }
        __syncthreads();
        if (tid < 416) {
            const int qg = tid % 13, cg = tid / 13;
            const int q0 = qg * 4, c0 = cg * 4;
            if (c0 < cn) {
                const int ci1 = min(c0 + 1, cn - 1);
                const int ci2 = min(c0 + 2, cn - 1);
                const int ci3 = min(c0 + 3, cn - 1);
                u64 blo = pack2f(sQW1[q0], sQW1[q0 + 1]);
                u64 bhi = pack2f(sQW1[q0 + 2], sQW1[q0 + 3]);
                u64 a0lo = blo, a0hi = bhi, a1lo = blo, a1hi = bhi;
                u64 a2lo = blo, a2hi = bhi, a3lo = blo, a3hi = bhi;
                #pragma unroll 4
                for (int d4 = 0; d4 < DD; d4 += 4) {
                    float4 x0 = *(const float4*)&sXc[c0  * XPAD + d4];
                    float4 x1 = *(const float4*)&sXc[ci1 * XPAD + d4];
                    float4 x2 = *(const float4*)&sXc[ci2 * XPAD + d4];
                    float4 x3 = *(const float4*)&sXc[ci3 * XPAD + d4];
                    const float* xa0 = (const float*)&x0;
                    const float* xa1 = (const float*)&x1;
                    const float* xa2 = (const float*)&x2;
                    const float* xa3 = (const float*)&x3;
                    #pragma unroll
                    for (int dd = 0; dd < 4; ++dd) {
                        longlong2 yv = *(const longlong2*)&sYqT[(d4 + dd) * QP + q0];
                        u64 v0 = pack2b(xa0[dd]);
                        u64 v1 = pack2b(xa1[dd]);
                        u64 v2 = pack2b(xa2[dd]);
                        u64 v3 = pack2b(xa3[dd]);
                        fma2(a0lo, v0, (u64)yv.x); fma2(a0hi, v0, (u64)yv.y);
                        fma2(a1lo, v1, (u64)yv.x); fma2(a1hi, v1, (u64)yv.y);
                        fma2(a2lo, v2, (u64)yv.x); fma2(a2hi, v2, (u64)yv.y);
                        fma2(a3lo, v3, (u64)yv.x); fma2(a3hi, v3, (u64)yv.y);
                    }
                }
                #define STORE_S(i, LO, HI)                                            \
                    if (c0 + (i) < cn) {                                              \
                        float* row = &sS[(cb + c0 + (i)) * SROW + q0];                \
                        float2 p = unpk(LO);                                          \
                        row[0] = p.x; row[1] = p.y;                                   \
                        p = unpk(HI);                                                 \
                        if (q0 + 2 < LQQ) row[2] = p.x;                               \
                        if (q0 + 3 < LQQ) row[3] = p.y;                               \
                    }
                STORE_S(0, a0lo, a0hi) STORE_S(1, a1lo, a1hi)
                STORE_S(2, a2lo, a2hi) STORE_S(3, a3lo, a3hi)
                #undef STORE_S
            }
        }
    }
    __syncthreads();

    // ---------------- Pass A: rmax (masked), E = exp(S - rmax) in place, rsum ----------------
    if (tid < LCC) {
        float* row = &sS[tid * SROW];
        float m = -3.0e38f;
        #pragma unroll 5
        for (int q = 0; q < LQQ; ++q) {
            float v = row[q] - (q < qlen ? 0.f : 1e12f);
            m = fmaxf(m, v);
        }
        float sum = 0.f;
        #pragma unroll 5
        for (int q = 0; q < LQQ; ++q) {
            float e = __expf(row[q] - m);      // unmasked E (needed for S_T cols)
            row[q] = e;
            if (q < qlen) sum += e;
        }
        sF[tid]    = m;                        // rmax for now
        sRInv[tid] = 1.f / sum;
    }
    __syncthreads();

    // ---------------- M = max_{c<clen} rmax[c]; f[c] = exp(rmax[c]-M) masked ----------------
    if (tid < 32) {
        float m = -3.0e38f;
        for (int c = tid; c < LCC; c += 32)
            if (c < clen) m = fmaxf(m, sF[c]);
        m = fmaxf(m, __shfl_xor_sync(0xffffffffu, m, 1));
        m = fmaxf(m, __shfl_xor_sync(0xffffffffu, m, 2));
        m = fmaxf(m, __shfl_xor_sync(0xffffffffu, m, 4));
        m = fmaxf(m, __shfl_xor_sync(0xffffffffu, m, 8));
        m = fmaxf(m, __shfl_xor_sync(0xffffffffu, m, 16));
        if (tid == 0) sQW1[50] = m;
    }
    __syncthreads();
    const float Mscal = sQW1[50];
    if (tid < LCC)
        sF[tid] = (tid < clen) ? __expf(sF[tid] - Mscal) : 0.f;
    __syncthreads();

    // ---------------- csum[q] = sum_c E[c,q]*f[c];  cinv = 1/csum ----------------
    {
        const int g = tid >> 3, s8 = tid & 7;
        float sum = 0.f;
        if (g < LQQ) {
            for (int c = s8; c < LCC; c += 8)
                sum = fmaf(sS[c * SROW + g], sF[c], sum);
        }
        sum += __shfl_xor_sync(0xffffffffu, sum, 1);
        sum += __shfl_xor_sync(0xffffffffu, sum, 2);
        sum += __shfl_xor_sync(0xffffffffu, sum, 4);
        if (g < LQQ && s8 == 0) sCInv[g] = 1.f / sum;
    }
    __syncthreads();

    // ---------------- S_T write: st[q,c] = E*f[c]*cinv[q] (all q, c-mask via f) ----------------
    float* st_g = out + RES_ELEMS + (size_t)NB * LCC * LQQ + (size_t)b * LQQ * LCC;
    for (int idx = tid; idx < LQQ * LCC; idx += NT) {
        int q = idx / LCC, c = idx - q * LCC;
        st_g[idx] = sS[c * SROW + q] * sF[c] * sCInv[q];
    }

    // ---------------- Phase 4: tmp[q,d] = cinv[q] * sum_c E[c,q]*(f[c]*xc[c,d]) ----------------
    const int dg = tid & 31;
    {
        const int qg = tid >> 5;
        const int q0 = qg * 4;
        const int qi0 = min(q0 + 0, LQQ - 1), qi1 = min(q0 + 1, LQQ - 1);
        const int qi2 = min(q0 + 2, LQQ - 1), qi3 = min(q0 + 3, LQQ - 1);
        u64 t0lo = 0, t0hi = 0, t1lo = 0, t1hi = 0;
        u64 t2lo = 0, t2hi = 0, t3lo = 0, t3hi = 0;
        for (int cb = 0; cb < LCC; cb += CCHUNK) {
            const int cn = min(CCHUNK, LCC - cb);
            __syncthreads();
            for (int idx = tid; idx < cn * 32; idx += NT) {
                int r  = idx >> 5;
                int c4 = (idx & 31) * 4;
                float f = sF[cb + r];
                float4 v = *(const float4*)&xcB[(size_t)(cb + r) * DD + c4];
                v.x *= f; v.y *= f; v.z *= f; v.w *= f;
                *(float4*)&sXc[r * XPAD + c4] = v;         // staged xc pre-scaled by f[c]
            }
            __syncthreads();
            if (q0 < LQQ) {
                #pragma unroll 2
                for (int c = 0; c < cn; ++c) {
                    longlong2 xv = *(const longlong2*)&sXc[c * XPAD + dg * 4];
                    const float* prow = &sS[(cb + c) * SROW];
                    u64 P0 = pack2b(prow[qi0]);
                    u64 P1 = pack2b(prow[qi1]);
                    u64 P2 = pack2b(prow[qi2]);
                    u64 P3 = pack2b(prow[qi3]);
                    fma2(t0lo, P0, (u64)xv.x); fma2(t0hi, P0, (u64)xv.y);
                    fma2(t1lo, P1, (u64)xv.x); fma2(t1hi, P1, (u64)xv.y);
                    fma2(t2lo, P2, (u64)xv.x); fma2(t2hi, P2, (u64)xv.y);
                    fma2(t3lo, P3, (u64)xv.x); fma2(t3hi, P3, (u64)xv.y);
                }
            }
        }
        __syncthreads();
        if (q0 < LQQ) {
            #define STORE_T(i, LO, HI)                                                \
                if (q0 + (i) < LQQ) {                                                 \
                    u64 cv = pack2b(sCInv[q0 + (i)]);                                 \
                    u64 lo = LO, hi = HI;                                             \
                    mul2(lo, lo, cv); mul2(hi, hi, cv);                               \
                    float2 p = unpk(lo);                                              \
                    float* trow = &sTmp[(q0 + (i)) * XPAD + dg * 4];                  \
                    trow[0] = p.x; trow[1] = p.y;                                     \
                    p = unpk(hi); trow[2] = p.x; trow[3] = p.y;                       \
                }
            STORE_T(0, t0lo, t0hi) STORE_T(1, t1lo, t1hi)
            STORE_T(2, t2lo, t2hi) STORE_T(3, t3lo, t3hi)
            #undef STORE_T
        }
    }
    __syncthreads();

    // ---------------- Mask invalid q in E + write S_bar = E*rinv ----------------
    float* sbar_g = out + RES_ELEMS + (size_t)b * LCC * LQQ;
    for (int idx = tid; idx < LCC * LQQ; idx += NT) {
        int c = idx / LQQ, q = idx - c * LQQ;
        float e = (q < qlen) ? sS[c * SROW + q] : 0.f;
        sS[c * SROW + q] = e;
        sbar_g[idx] = e * sRInv[c];
    }
    __syncthreads();

    // ---------------- Phase 5: c2q = (E*rinv)@xq, q2c = (E*rinv)@tmp, fused epilogue ----------------
    {
        const int cg = tid >> 5;               // warp-uniform: E loads broadcast
        for (int cb = 0; cb < LCC; cb += 64) {
            const int c0 = cb + cg * 4;
            if (c0 >= LCC) continue;
            u64 a10lo = 0, a10hi = 0, a11lo = 0, a11hi = 0;
            u64 a12lo = 0, a12hi = 0, a13lo = 0, a13hi = 0;
            u64 a20lo = 0, a20hi = 0, a21lo = 0, a21hi = 0;
            u64 a22lo = 0, a22hi = 0, a23lo = 0, a23hi = 0;
            #pragma unroll 2
            for (int q = 0; q < LQQ; ++q) {
                longlong2 xqv = *(const longlong2*)&sXq[q * XPAD + dg * 4];
                longlong2 tv  = *(const longlong2*)&sTmp[q * XPAD + dg * 4];
                u64 S0 = pack2b(sS[(c0 + 0) * SROW + q]);
                u64 S1 = pack2b(sS[(c0 + 1) * SROW + q]);
                u64 S2 = pack2b(sS[(c0 + 2) * SROW + q]);
                u64 S3 = pack2b(sS[(c0 + 3) * SROW + q]);
                fma2(a10lo, S0, (u64)xqv.x); fma2(a10hi, S0, (u64)xqv.y);
                fma2(a11lo, S1, (u64)xqv.x); fma2(a11hi, S1, (u64)xqv.y);
                fma2(a12lo, S2, (u64)xqv.x); fma2(a12hi, S2, (u64)xqv.y);
                fma2(a13lo, S3, (u64)xqv.x); fma2(a13hi, S3, (u64)xqv.y);
                fma2(a20lo, S0, (u64)tv.x);  fma2(a20hi, S0, (u64)tv.y);
                fma2(a21lo, S1, (u64)tv.x);  fma2(a21hi, S1, (u64)tv.y);
                fma2(a22lo, S2, (u64)tv.x);  fma2(a22hi, S2, (u64)tv.y);
                fma2(a23lo, S3, (u64)tv.x);  fma2(a23hi, S3, (u64)tv.y);
            }
            #define EPI(i, L1, H1, L2, H2)                                             \
                {                                                                      \
                    int c = c0 + (i);                                                  \
                    u64 rv = pack2b(sRInv[c]);                                         \
                    u64 l1 = L1, h1 = H1, l2 = L2, h2 = H2;                            \
                    mul2(l1, l1, rv); mul2(h1, h1, rv);                                \
                    mul2(l2, l2, rv); mul2(h2, h2, rv);                                \
                    float4 xcv = *(const float4*)&xcB[(size_t)c * DD + dg * 4];        \
                    float* orow = out + ((size_t)(b * LCC + c)) * (4 * DD);            \
                    float2 plo = unpk(l1), phi = unpk(h1);                             \
                    float4 A1 = make_float4(plo.x, plo.y, phi.x, phi.y);               \
                    plo = unpk(l2); phi = unpk(h2);                                    \
                    float4 A2 = make_float4(plo.x, plo.y, phi.x, phi.y);               \
                    *(float4*)&orow[dg * 4] = xcv;                                     \
                    *(float4*)&orow[DD + dg * 4] = A1;                                 \
                    float4 m1 = make_float4(xcv.x * A1.x, xcv.y * A1.y,                \
                                            xcv.z * A1.z, xcv.w * A1.w);               \
                    *(float4*)&orow[2 * DD + dg * 4] = m1;                             \
                    float4 m2 = make_float4(xcv.x * A2.x, xcv.y * A2.y,                \
                                            xcv.z * A2.z, xcv.w * A2.w);               \
                    *(float4*)&orow[3 * DD + dg * 4] = m2;                             \
                }
            EPI(0, a10lo, a10hi, a20lo, a20hi)
            EPI(1, a11lo, a11hi, a21lo, a21hi)
            EPI(2, a12lo, a12hi, a22lo, a22hi)
            EPI(3, a13lo, a13hi, a23lo, a23hi)
            #undef EPI
        }
    }
}

extern "C" void kernel_launch(void* const* d_in, const int* in_sizes, int n_in,
                              void* d_out, int out_size)
{
    const float* xc  = (const float*)d_in[0];
    const float* xq  = (const float*)d_in[1];
    const float* W0  = (const float*)d_in[2];
    const float* W1  = (const float*)d_in[3];
    const float* W2  = (const float*)d_in[4];
    const int* clen  = (const int*)d_in[5];
    const int* qlen  = (const int*)d_in[6];
    float* out = (float*)d_out;

    const int smem_bytes = SMEM_FLOATS * (int)sizeof(float);
    cudaFuncSetAttribute(cqa_kernel, cudaFuncAttributeMaxDynamicSharedMemorySize, smem_bytes);
    cqa_kernel<<<NB, NT, smem_bytes>>>(xc, xq, W0, W1, W2, clen, qlen, out);
}

// round 4
// speedup vs baseline: 1.4897x; 1.0350x over previous
#include <cuda_runtime.h>
#include <math.h>

#define NB   256
#define LCC  400
#define LQQ  50
#define DD   128
#define ETP  404     // E^T row stride (floats): ET[q][c], q<50
#define XPAD 132     // padded row stride for D-vectors
#define QP   52      // padded q stride for transposed Yq
#define CCHUNK 128
#define NT   512

// smem offsets (floats)
#define OFF_ET   0                    // 50*404  = 20200
#define OFF_XQ   20200                // 52*132  = 6864
#define OFF_YQT  27064                // 128*52  = 6656
#define OFF_XC   33720                // 128*132 = 16896 -> ends 50616
#define OFF_TMP  (OFF_XC + 4096)      // 50*132 = 6600, aliased in sXc rows >= 31
#define OFF_F    50616                // 400 (rmax then f[c])
#define OFF_RINV 51016                // 400
#define OFF_CINV 51416                // 52
#define OFF_QW1  51468                // 64 (slot 56 = scalar M)
#define SMEM_FLOATS 51532             // 206128 bytes

#define RES_ELEMS ((size_t)NB * LCC * 4 * DD)      // 52,428,800

typedef unsigned long long u64;

__device__ __forceinline__ u64 pack2b(float v) {
    u64 r; asm("mov.b64 %0, {%1, %1};" : "=l"(r) : "f"(v)); return r;
}
__device__ __forceinline__ u64 pack2f(float a, float b) {
    u64 r; asm("mov.b64 %0, {%1, %2};" : "=l"(r) : "f"(a), "f"(b)); return r;
}
__device__ __forceinline__ void fma2(u64 &d, u64 a, u64 b) {
    asm("fma.rn.f32x2 %0, %1, %2, %3;" : "=l"(d) : "l"(a), "l"(b), "l"(d));
}
__device__ __forceinline__ void mul2(u64 &d, u64 a, u64 b) {
    asm("mul.rn.f32x2 %0, %1, %2;" : "=l"(d) : "l"(a), "l"(b));
}
__device__ __forceinline__ float2 unpk(u64 v) {
    float2 r; asm("mov.b64 {%0, %1}, %2;" : "=f"(r.x), "=f"(r.y) : "l"(v)); return r;
}

__global__ __launch_bounds__(NT, 1)
void cqa_kernel(const float* __restrict__ xc_g, const float* __restrict__ xq_g,
                const float* __restrict__ W0, const float* __restrict__ W1,
                const float* __restrict__ W2, const int* __restrict__ clen_g,
                const int* __restrict__ qlen_g, float* __restrict__ out)
{
    extern __shared__ float sm[];
    const int b   = blockIdx.x;
    const int tid = threadIdx.x;
    const float* xcB = xc_g + (size_t)b * LCC * DD;
    const float* xqB = xq_g + (size_t)b * LQQ * DD;
    const int clen = clen_g[b];
    const int qlen = qlen_g[b];

    float* sET   = sm + OFF_ET;
    float* sXq   = sm + OFF_XQ;
    float* sYqT  = sm + OFF_YQT;
    float* sXc   = sm + OFF_XC;
    float* sTmp  = sm + OFF_TMP;
    float* sF    = sm + OFF_F;
    float* sRInv = sm + OFF_RINV;
    float* sCInv = sm + OFF_CINV;
    float* sQW1  = sm + OFF_QW1;

    // ---------------- Phase 0: stage xq + build YqT = (xq*W2 + W0)^T ----------------
    for (int idx = tid; idx < LQQ * 32; idx += NT) {
        int q  = idx >> 5;
        int c4 = (idx & 31) * 4;
        float4 v  = *(const float4*)&xqB[q * DD + c4];
        *(float4*)&sXq[q * XPAD + c4] = v;
        float4 w2 = *(const float4*)&W2[c4];
        float4 w0 = *(const float4*)&W0[c4];
        sYqT[(c4 + 0) * QP + q] = fmaf(v.x, w2.x, w0.x);
        sYqT[(c4 + 1) * QP + q] = fmaf(v.y, w2.y, w0.y);
        sYqT[(c4 + 2) * QP + q] = fmaf(v.z, w2.z, w0.z);
        sYqT[(c4 + 3) * QP + q] = fmaf(v.w, w2.w, w0.w);
    }
    // zero pad columns 50,51 of YqT (read by phase-1 vector loads)
    for (int d = tid; d < DD; d += NT) {
        sYqT[d * QP + 50] = 0.f;
        sYqT[d * QP + 51] = 0.f;
    }
    if (tid < 64) sQW1[tid] = 0.f;
    __syncthreads();
    // qW1[q] = xq[q] . W1
    if (tid < LQQ) {
        float s = 0.f;
        #pragma unroll 8
        for (int d = 0; d < DD; d += 4) {
            float4 xv = *(const float4*)&sXq[tid * XPAD + d];
            float4 wv = *(const float4*)&W1[d];
            s = fmaf(xv.x, wv.x, s); s = fmaf(xv.y, wv.y, s);
            s = fmaf(xv.z, wv.z, s); s = fmaf(xv.w, wv.w, s);
        }
        sQW1[tid] = s;
    }

    // ---------------- Phase 1: S[c,q] = qW1[q] + xc . YqT ; store transposed to ET ----------------
    for (int cb = 0; cb < LCC; cb += CCHUNK) {
        const int cn = min(CCHUNK, LCC - cb);
        __syncthreads();
        for (int idx = tid; idx < cn * 32; idx += NT) {
            int r  = idx >> 5;
            int c4 = (idx & 31) * 4;
            *(float4*)&sXc[r * XPAD + c4] = *(const float4*)&xcB[(size_t)(cb + r) * DD + c4];
        }
        __syncthreads();
        if (tid < 416) {
            const int qg = tid % 13, cg = tid / 13;
            const int q0 = qg * 4, c0 = cg * 4;
            if (c0 < cn) {
                u64 blo = pack2f(sQW1[q0], sQW1[q0 + 1]);
                u64 bhi = pack2f(sQW1[q0 + 2], sQW1[q0 + 3]);
                u64 a0lo = blo, a0hi = bhi, a1lo = blo, a1hi = bhi;
                u64 a2lo = blo, a2hi = bhi, a3lo = blo, a3hi = bhi;
                #pragma unroll 4
                for (int d4 = 0; d4 < DD; d4 += 4) {
                    float4 x0 = *(const float4*)&sXc[(c0 + 0) * XPAD + d4];
                    float4 x1 = *(const float4*)&sXc[(c0 + 1) * XPAD + d4];
                    float4 x2 = *(const float4*)&sXc[(c0 + 2) * XPAD + d4];
                    float4 x3 = *(const float4*)&sXc[(c0 + 3) * XPAD + d4];
                    const float* xa0 = (const float*)&x0;
                    const float* xa1 = (const float*)&x1;
                    const float* xa2 = (const float*)&x2;
                    const float* xa3 = (const float*)&x3;
                    #pragma unroll
                    for (int dd = 0; dd < 4; ++dd) {
                        longlong2 yv = *(const longlong2*)&sYqT[(d4 + dd) * QP + q0];
                        u64 v0 = pack2b(xa0[dd]);
                        u64 v1 = pack2b(xa1[dd]);
                        u64 v2 = pack2b(xa2[dd]);
                        u64 v3 = pack2b(xa3[dd]);
                        fma2(a0lo, v0, (u64)yv.x); fma2(a0hi, v0, (u64)yv.y);
                        fma2(a1lo, v1, (u64)yv.x); fma2(a1hi, v1, (u64)yv.y);
                        fma2(a2lo, v2, (u64)yv.x); fma2(a2hi, v2, (u64)yv.y);
                        fma2(a3lo, v3, (u64)yv.x); fma2(a3hi, v3, (u64)yv.y);
                    }
                }
                // register transpose -> ET[q][c0..c0+3]
                {
                    const int cgl = cb + c0;
                    float2 p0 = unpk(a0lo), p1 = unpk(a1lo), p2 = unpk(a2lo), p3 = unpk(a3lo);
                    *(float4*)&sET[(q0 + 0) * ETP + cgl] = make_float4(p0.x, p1.x, p2.x, p3.x);
                    if (q0 + 1 < LQQ)
                        *(float4*)&sET[(q0 + 1) * ETP + cgl] = make_float4(p0.y, p1.y, p2.y, p3.y);
                    p0 = unpk(a0hi); p1 = unpk(a1hi); p2 = unpk(a2hi); p3 = unpk(a3hi);
                    if (q0 + 2 < LQQ)
                        *(float4*)&sET[(q0 + 2) * ETP + cgl] = make_float4(p0.x, p1.x, p2.x, p3.x);
                    if (q0 + 3 < LQQ)
                        *(float4*)&sET[(q0 + 3) * ETP + cgl] = make_float4(p0.y, p1.y, p2.y, p3.y);
                }
            }
        }
    }
    __syncthreads();

    // ---------------- Pass A: per-c masked max, E = exp(S - rmax) in place, masked rsum ----------------
    if (tid < LCC) {
        const int c = tid;
        float m = -3.0e38f;
        #pragma unroll 5
        for (int q = 0; q < LQQ; ++q) {
            float v = sET[q * ETP + c] - (q < qlen ? 0.f : 1e12f);
            m = fmaxf(m, v);
        }
        float sum = 0.f;
        #pragma unroll 5
        for (int q = 0; q < LQQ; ++q) {
            float e = __expf(sET[q * ETP + c] - m);   // unmasked E
            sET[q * ETP + c] = e;
            if (q < qlen) sum += e;
        }
        sF[c]    = m;              // rmax for now
        sRInv[c] = 1.f / sum;
    }
    __syncthreads();

    // ---------------- M = max_{c<clen} rmax[c];  f[c] = exp(rmax[c]-M), 0 for c>=clen ----------------
    if (tid < 32) {
        float m = -3.0e38f;
        for (int c = tid; c < LCC; c += 32)
            if (c < clen) m = fmaxf(m, sF[c]);
        m = fmaxf(m, __shfl_xor_sync(0xffffffffu, m, 1));
        m = fmaxf(m, __shfl_xor_sync(0xffffffffu, m, 2));
        m = fmaxf(m, __shfl_xor_sync(0xffffffffu, m, 4));
        m = fmaxf(m, __shfl_xor_sync(0xffffffffu, m, 8));
        m = fmaxf(m, __shfl_xor_sync(0xffffffffu, m, 16));
        if (tid == 0) sQW1[56] = m;
    }
    __syncthreads();
    const float Mscal = sQW1[56];
    if (tid < LCC)
        sF[tid] = (tid < clen) ? __expf(sF[tid] - Mscal) : 0.f;
    __syncthreads();

    // ---------------- csum[q] = sum_c E[q][c]*f[c];  cinv = 1/csum ----------------
    {
        const int g = tid >> 3, s8 = tid & 7;
        float sum = 0.f;
        if (g < LQQ) {
            const float* row = &sET[g * ETP];
            for (int c = s8; c < LCC; c += 8)
                sum = fmaf(row[c], sF[c], sum);
        }
        sum += __shfl_xor_sync(0xffffffffu, sum, 1);
        sum += __shfl_xor_sync(0xffffffffu, sum, 2);
        sum += __shfl_xor_sync(0xffffffffu, sum, 4);
        if (g < LQQ && s8 == 0) sCInv[g] = 1.f / sum;
    }
    __syncthreads();

    // ---------------- S_T write: st[q,c] = E[q][c]*f[c]*cinv[q]  (contiguous) ----------------
    float* st_g = out + RES_ELEMS + (size_t)NB * LCC * LQQ + (size_t)b * LQQ * LCC;
    for (int idx = tid; idx < LQQ * LCC; idx += NT) {
        int q = idx / LCC, c = idx - q * LCC;
        st_g[idx] = sET[q * ETP + c] * sF[c] * sCInv[q];
    }

    // ---------------- Phase 4: tmp[q,d] = cinv[q] * sum_c E[q][c]*(f[c]*xc[c,d]) ----------------
    const int dg = tid & 31;
    {
        const int qg = tid >> 5;
        const int q0 = qg * 4;
        const int qi0 = min(q0 + 0, LQQ - 1), qi1 = min(q0 + 1, LQQ - 1);
        const int qi2 = min(q0 + 2, LQQ - 1), qi3 = min(q0 + 3, LQQ - 1);
        u64 t0lo = 0, t0hi = 0, t1lo = 0, t1hi = 0;
        u64 t2lo = 0, t2hi = 0, t3lo = 0, t3hi = 0;
        for (int cb = 0; cb < LCC; cb += CCHUNK) {
            const int cn = min(CCHUNK, LCC - cb);
            __syncthreads();
            for (int idx = tid; idx < cn * 32; idx += NT) {
                int r  = idx >> 5;
                int c4 = (idx & 31) * 4;
                float f = sF[cb + r];
                float4 v = *(const float4*)&xcB[(size_t)(cb + r) * DD + c4];
                v.x *= f; v.y *= f; v.z *= f; v.w *= f;
                *(float4*)&sXc[r * XPAD + c4] = v;
            }
            __syncthreads();
            if (qg < 13) {
                for (int c = 0; c < cn; c += 4) {
                    float4 e0 = *(const float4*)&sET[qi0 * ETP + cb + c];
                    float4 e1 = *(const float4*)&sET[qi1 * ETP + cb + c];
                    float4 e2 = *(const float4*)&sET[qi2 * ETP + cb + c];
                    float4 e3 = *(const float4*)&sET[qi3 * ETP + cb + c];
                    const float* f0 = (const float*)&e0;
                    const float* f1 = (const float*)&e1;
                    const float* f2 = (const float*)&e2;
                    const float* f3 = (const float*)&e3;
                    #pragma unroll
                    for (int cc = 0; cc < 4; ++cc) {
                        longlong2 xv = *(const longlong2*)&sXc[(c + cc) * XPAD + dg * 4];
                        u64 P0 = pack2b(f0[cc]);
                        u64 P1 = pack2b(f1[cc]);
                        u64 P2 = pack2b(f2[cc]);
                        u64 P3 = pack2b(f3[cc]);
                        fma2(t0lo, P0, (u64)xv.x); fma2(t0hi, P0, (u64)xv.y);
                        fma2(t1lo, P1, (u64)xv.x); fma2(t1hi, P1, (u64)xv.y);
                        fma2(t2lo, P2, (u64)xv.x); fma2(t2hi, P2, (u64)xv.y);
                        fma2(t3lo, P3, (u64)xv.x); fma2(t3hi, P3, (u64)xv.y);
                    }
                }
            }
        }
        __syncthreads();
        if (qg < 13) {
            #define STORE_T(i, LO, HI)                                                \
                if (q0 + (i) < LQQ) {                                                 \
                    u64 cv = pack2b(sCInv[q0 + (i)]);                                 \
                    u64 lo = LO, hi = HI;                                             \
                    mul2(lo, lo, cv); mul2(hi, hi, cv);                               \
                    float2 p = unpk(lo);                                              \
                    float* trow = &sTmp[(q0 + (i)) * XPAD + dg * 4];                  \
                    trow[0] = p.x; trow[1] = p.y;                                     \
                    p = unpk(hi); trow[2] = p.x; trow[3] = p.y;                       \
                }
            STORE_T(0, t0lo, t0hi) STORE_T(1, t1lo, t1hi)
            STORE_T(2, t2lo, t2hi) STORE_T(3, t3lo, t3hi)
            #undef STORE_T
        }
    }
    __syncthreads();

    // ---------------- Zero invalid-q rows of E, then S_bar = E*rinv ----------------
    for (int idx = tid; idx < LQQ * LCC; idx += NT) {
        int q = idx / LCC;
        if (q >= qlen) sET[q * ETP + (idx - q * LCC)] = 0.f;
    }
    __syncthreads();
    float* sbar_g = out + RES_ELEMS + (size_t)b * LCC * LQQ;
    for (int idx = tid; idx < LCC * LQQ; idx += NT) {
        int c = idx / LQQ, q = idx - c * LQQ;
        sbar_g[idx] = sET[q * ETP + c] * sRInv[c];
    }
    __syncthreads();

    // ---------------- Phase 5: c2q = (E*rinv)@xq, q2c = (E*rinv)@tmp, fused epilogue ----------------
    {
        const int cg = tid >> 5;                   // warp-uniform
        for (int cb = 0; cb < LCC; cb += 128) {
            const int c0 = cb + cg * 8;
            if (c0 >= LCC) continue;
            u64 A1lo[8], A1hi[8], A2lo[8], A2hi[8];
            #pragma unroll
            for (int i = 0; i < 8; ++i) { A1lo[i] = 0; A1hi[i] = 0; A2lo[i] = 0; A2hi[i] = 0; }
            #pragma unroll 2
            for (int q = 0; q < LQQ; ++q) {
                longlong2 xqv = *(const longlong2*)&sXq[q * XPAD + dg * 4];
                longlong2 tv  = *(const longlong2*)&sTmp[q * XPAD + dg * 4];
                float4 sa = *(const float4*)&sET[q * ETP + c0];
                float4 sb = *(const float4*)&sET[q * ETP + c0 + 4];
                const float* sv0 = (const float*)&sa;
                const float* sv1 = (const float*)&sb;
                #pragma unroll
                for (int i = 0; i < 4; ++i) {
                    u64 S = pack2b(sv0[i]);
                    fma2(A1lo[i], S, (u64)xqv.x); fma2(A1hi[i], S, (u64)xqv.y);
                    fma2(A2lo[i], S, (u64)tv.x);  fma2(A2hi[i], S, (u64)tv.y);
                }
                #pragma unroll
                for (int i = 0; i < 4; ++i) {
                    u64 S = pack2b(sv1[i]);
                    fma2(A1lo[4 + i], S, (u64)xqv.x); fma2(A1hi[4 + i], S, (u64)xqv.y);
                    fma2(A2lo[4 + i], S, (u64)tv.x);  fma2(A2hi[4 + i], S, (u64)tv.y);
                }
            }
            #pragma unroll
            for (int i = 0; i < 8; ++i) {
                const int c = c0 + i;
                u64 rv = pack2b(sRInv[c]);
                u64 l1 = A1lo[i], h1 = A1hi[i], l2 = A2lo[i], h2 = A2hi[i];
                mul2(l1, l1, rv); mul2(h1, h1, rv);
                mul2(l2, l2, rv); mul2(h2, h2, rv);
                float4 xcv = *(const float4*)&xcB[(size_t)c * DD + dg * 4];
                float* orow = out + ((size_t)(b * LCC + c)) * (4 * DD);
                float2 plo = unpk(l1), phi = unpk(h1);
                float4 A1 = make_float4(plo.x, plo.y, phi.x, phi.y);
                plo = unpk(l2); phi = unpk(h2);
                float4 A2 = make_float4(plo.x, plo.y, phi.x, phi.y);
                *(float4*)&orow[dg * 4] = xcv;
                *(float4*)&orow[DD + dg * 4] = A1;
                float4 m1 = make_float4(xcv.x * A1.x, xcv.y * A1.y,
                                        xcv.z * A1.z, xcv.w * A1.w);
                *(float4*)&orow[2 * DD + dg * 4] = m1;
                float4 m2 = make_float4(xcv.x * A2.x, xcv.y * A2.y,
                                        xcv.z * A2.z, xcv.w * A2.w);
                *(float4*)&orow[3 * DD + dg * 4] = m2;
            }
        }
    }
}

extern "C" void kernel_launch(void* const* d_in, const int* in_sizes, int n_in,
                              void* d_out, int out_size)
{
    const float* xc  = (const float*)d_in[0];
    const float* xq  = (const float*)d_in[1];
    const float* W0  = (const float*)d_in[2];
    const float* W1  = (const float*)d_in[3];
    const float* W2  = (const float*)d_in[4];
    const int* clen  = (const int*)d_in[5];
    const int* qlen  = (const int*)d_in[6];
    float* out = (float*)d_out;

    const int smem_bytes = SMEM_FLOATS * (int)sizeof(float);
    cudaFuncSetAttribute(cqa_kernel, cudaFuncAttributeMaxDynamicSharedMemorySize, smem_bytes);
    cqa_kernel<<<NB, NT, smem_bytes>>>(xc, xq, W0, W1, W2, clen, qlen, out);
}